// round 6
// baseline (speedup 1.0000x reference)
#include <cuda_runtime.h>
#include <cstdint>

// Identity op: reference output == input X (the torch module's loop writes
// are dead; output is exactly the input tensor).
//
// R3/R4 established the hand-rolled SM copy is pinned at ~7.1 TB/s effective
// (37.5 us kernel) regardless of VPT / occupancy / cache hints -> SM-path
// copy roofline. This round tests the driver memcpy path: cudaMemcpyAsync
// D2D is graph-capturable (becomes a memcpy node) and may use the
// copy-engine / driver-tuned copy, plus lower node overhead.

extern "C" void kernel_launch(void* const* d_in, const int* in_sizes, int n_in,
                              void* d_out, int out_size) {
    const void* x = d_in[0];
    // out_size = element count of fp32 output (33,554,432 expected).
    size_t bytes = (size_t)out_size * sizeof(float);
    cudaMemcpyAsync(d_out, x, bytes, cudaMemcpyDeviceToDevice, 0);
}

// round 7
// speedup vs baseline: 1.0425x; 1.0425x over previous
#include <cuda_runtime.h>
#include <cstdint>

// Identity op: reference output == input X. Pure 128 MiB HBM copy.
// R3-R5 establish SM copy / driver memcpy all pin at ~7.1 TB/s mixed r/w.
// This round: 256-bit global ld/st (sm_100a ld.global.v8.f32) to halve the
// request count per byte and improve DRAM burst efficiency at the margin.

__device__ __forceinline__ void ldg256(const float* __restrict__ p, float* v) {
    asm volatile(
        "ld.global.nc.v8.f32 {%0,%1,%2,%3,%4,%5,%6,%7}, [%8];"
        : "=f"(v[0]), "=f"(v[1]), "=f"(v[2]), "=f"(v[3]),
          "=f"(v[4]), "=f"(v[5]), "=f"(v[6]), "=f"(v[7])
        : "l"(p));
}

__device__ __forceinline__ void stg256(float* __restrict__ p, const float* v) {
    asm volatile(
        "st.global.v8.f32 [%0], {%1,%2,%3,%4,%5,%6,%7,%8};"
        :: "l"(p),
           "f"(v[0]), "f"(v[1]), "f"(v[2]), "f"(v[3]),
           "f"(v[4]), "f"(v[5]), "f"(v[6]), "f"(v[7])
        : "memory");
}

constexpr int V8PT = 4;  // 4 x 32B = 128 B per thread

__global__ void copy_v8_kernel(const float* __restrict__ src,
                               float* __restrict__ dst,
                               long long n8) {   // count of float8 chunks
    long long base = (long long)blockIdx.x * (blockDim.x * V8PT) + threadIdx.x;

    float v[V8PT][8];
    #pragma unroll
    for (int j = 0; j < V8PT; j++) {
        long long i = base + (long long)j * blockDim.x;
        if (i < n8) ldg256(src + i * 8, v[j]);
    }
    #pragma unroll
    for (int j = 0; j < V8PT; j++) {
        long long i = base + (long long)j * blockDim.x;
        if (i < n8) stg256(dst + i * 8, v[j]);
    }
}

// Scalar fallback for non-32B-divisible sizes (not expected: n = 2^25).
__global__ void copy_f1_kernel(const float* __restrict__ src,
                               float* __restrict__ dst,
                               long long n) {
    long long i = (long long)blockIdx.x * blockDim.x + threadIdx.x;
    long long stride = (long long)gridDim.x * blockDim.x;
    for (; i < n; i += stride) dst[i] = src[i];
}

extern "C" void kernel_launch(void* const* d_in, const int* in_sizes, int n_in,
                              void* d_out, int out_size) {
    const float* x = (const float*)d_in[0];
    float* out = (float*)d_out;
    long long n = (long long)out_size;   // 33,554,432 floats expected

    if ((n & 7) == 0 && (((uintptr_t)x | (uintptr_t)out) & 31) == 0) {
        long long n8 = n >> 3;
        const int threads = 256;
        const long long per_block = (long long)threads * V8PT;  // 1024 float8
        long long blocks_ll = (n8 + per_block - 1) / per_block; // 4096 expected
        int blocks = (blocks_ll > 1048576LL) ? 1048576 : (int)blocks_ll;
        copy_v8_kernel<<<blocks, threads>>>(x, out, n8);
    } else {
        int blocks = (int)(((n >> 2) + 255) / 256);
        if (blocks < 1) blocks = 1;
        if (blocks > 262144) blocks = 262144;
        copy_f1_kernel<<<blocks, 256>>>(x, out, n);
    }
}